// round 2
// baseline (speedup 1.0000x reference)
#include <cuda_runtime.h>
#include <cstdint>

#define SS 200
#define DD 64
#define NOUT 18
#define NT 256
#define STRIDE 68          // padded floats per embed row (conflict-free)

typedef unsigned long long ull;

// dynamic smem layout (floats):
//   [0, 13600)          s_emb[200 * 68]          (aliased by s_comb after phase 3)
//   [13600, 15200)      s_p[200 * 8]
//   [15200, 15520)      s_aw[5 * 64]
#define OFF_EMB 0
#define OFF_P   13600
#define OFF_AW  15200
#define DYN_FLOATS 15520

__device__ float g_loss_part[4096];
__device__ unsigned int g_ticket = 0;

__device__ __forceinline__ ull ffma2(ull a, ull b, ull c) {
    ull d; asm("fma.rn.f32x2 %0, %1, %2, %3;" : "=l"(d) : "l"(a), "l"(b), "l"(c)); return d;
}
__device__ __forceinline__ ull pack2(float x, float y) {
    ull r; asm("mov.b64 %0, {%1, %2};" : "=l"(r) : "f"(x), "f"(y)); return r;
}
__device__ __forceinline__ void unpack2(ull v, float& x, float& y) {
    asm("mov.b64 {%0, %1}, %2;" : "=f"(x), "=f"(y) : "l"(v));
}

__global__ __launch_bounds__(NT, 3) void tan_kernel(
    const int* __restrict__ x, const float* __restrict__ y,
    const float* __restrict__ emb, const float* __restrict__ attw,
    const float* __restrict__ attb,
    const float* __restrict__ W0, const float* __restrict__ W1,
    const float* __restrict__ W2, const float* __restrict__ W3,
    const float* __restrict__ W4,
    float* __restrict__ out, int out_size)
{
    extern __shared__ float dyn[];
    __shared__ float s_dcomb[8 * 5];
    __shared__ float s_urep[5 * DD];
    __shared__ float s_deninv[5];
    __shared__ float s_wu[NOUT];
    __shared__ float s_lossi[5];
    __shared__ float s_red[NT];
    __shared__ int   s_last;

    const int b    = blockIdx.x;
    const int t    = threadIdx.x;
    const int lane = t & 31;
    const int warp = t >> 5;

    const uint32_t sbase = (uint32_t)__cvta_generic_to_shared(dyn);
    const uint32_t a_emb = sbase + OFF_EMB * 4;
    const uint32_t a_p   = sbase + OFF_P * 4;
    const uint32_t a_aw  = sbase + OFF_AW * 4;

    // stage attention weights into smem (5*64 = 320 floats)
    if (t < 64) {
#pragma unroll
        for (int k = 0; k < 5; ++k)
            dyn[OFF_AW + k * 64 + t] = __ldg(&attw[k * DD + t]);
    }
    __syncthreads();

    // ================= Phase A: gather + attention (thread per row) =========
    if (t < SS) {
        int row = __ldg(&x[b * SS + t]);
        const float* gp = emb + (size_t)row * DD;

        ull acc[5];
#pragma unroll
        for (int k = 0; k < 5; ++k) acc[k] = 0ull;

        uint32_t dst = a_emb + (uint32_t)(t * STRIDE) * 4;
#pragma unroll 4
        for (int c = 0; c < 16; ++c) {
            ull e01, e23;
            asm("ld.global.nc.v2.u64 {%0, %1}, [%2];"
                : "=l"(e01), "=l"(e23) : "l"(gp + c * 4));
            asm volatile("st.shared.v2.u64 [%0], {%1, %2};"
                         :: "r"(dst + c * 16), "l"(e01), "l"(e23));
#pragma unroll
            for (int k = 0; k < 5; ++k) {
                ull w01, w23;
                asm("ld.shared.v2.u64 {%0, %1}, [%2];"
                    : "=l"(w01), "=l"(w23)
                    : "r"(a_aw + (uint32_t)(k * 64 + c * 4) * 4));
                acc[k] = ffma2(e01, w01, acc[k]);
                acc[k] = ffma2(e23, w23, acc[k]);
            }
        }

        // horizontal finish + bias + tanh + exp  (|tanh|<=1 so no max-sub)
        float p[5];
#pragma unroll
        for (int k = 0; k < 5; ++k) {
            float lo, hi;
            unpack2(acc[k], lo, hi);
            float u  = lo + hi + __ldg(&attb[k]);
            float ex = __expf(2.0f * u);
            float th = 1.0f - __fdividef(2.0f, ex + 1.0f);
            p[k] = __expf(th);
        }
        float4 pv4 = make_float4(p[0], p[1], p[2], p[3]);
        *(float4*)&dyn[OFF_P + t * 8] = pv4;
        dyn[OFF_P + t * 8 + 4] = p[4];
    }
    __syncthreads();

    // ================= Phase 3: softmax numerators + denominators ===========
    // 8 warps x 25 rows, lane = d-pair. acc packed (x,y) via FFMA2.
    ull ac[5];
    float ds[5];
#pragma unroll
    for (int k = 0; k < 5; ++k) { ac[k] = 0ull; ds[k] = 0.f; }
    {
        const int base = warp * 25;
#pragma unroll 5
        for (int i = 0; i < 25; ++i) {
            int s = base + i;
            float4 pv = *(const float4*)&dyn[OFF_P + s * 8];
            float  p4 = dyn[OFF_P + s * 8 + 4];
            ull e2;
            asm("ld.shared.b64 %0, [%1];"
                : "=l"(e2) : "r"(a_emb + (uint32_t)(s * STRIDE + lane * 2) * 4));
            ac[0] = ffma2(e2, pack2(pv.x, pv.x), ac[0]);
            ac[1] = ffma2(e2, pack2(pv.y, pv.y), ac[1]);
            ac[2] = ffma2(e2, pack2(pv.z, pv.z), ac[2]);
            ac[3] = ffma2(e2, pack2(pv.w, pv.w), ac[3]);
            ac[4] = ffma2(e2, pack2(p4,   p4),   ac[4]);
            ds[0] += pv.x; ds[1] += pv.y; ds[2] += pv.z; ds[3] += pv.w; ds[4] += p4;
        }
    }
    __syncthreads();   // s_emb reads done -> safe to alias with s_comb

    // per-warp partials: s_comb aliases s_emb region. layout [(w*5+k)*32+lane] x float2
#pragma unroll
    for (int k = 0; k < 5; ++k) {
        uint32_t addr = a_emb + (uint32_t)(((warp * 5 + k) * 32 + lane) * 8);
        asm volatile("st.shared.u64 [%0], %1;" :: "r"(addr), "l"(ac[k]));
    }
    if (lane == 0) {
#pragma unroll
        for (int k = 0; k < 5; ++k) s_dcomb[warp * 5 + k] = ds[k];
    }
    __syncthreads();

    if (t < 5) {
        float dn = 0.f;
#pragma unroll
        for (int w = 0; w < 8; ++w) dn += s_dcomb[w * 5 + t];
        s_deninv[t] = 1.0f / dn;
    }
    if (t < 160) {
        int k = t >> 5, d2 = t & 31;
        float sx = 0.f, sy = 0.f;
#pragma unroll
        for (int w = 0; w < 8; ++w) {
            float2 v = *(const float2*)&dyn[OFF_EMB + ((w * 5 + k) * 32 + d2) * 2];
            sx += v.x; sy += v.y;
        }
        s_urep[k * DD + d2 * 2]     = sx;
        s_urep[k * DD + d2 * 2 + 1] = sy;
    }
    __syncthreads();

    // ================= Phase 5: W_user = user_rep @ Wi^T ====================
    for (int j = warp; j < NOUT; j += 8) {
        int i = (j < 2) ? 0 : (j < 6) ? 1 : (j < 10) ? 2 : (j < 12) ? 3 : 4;
        int bse = (i == 0) ? 0 : (i == 1) ? 2 : (i == 2) ? 6 : (i == 3) ? 10 : 12;
        int r = j - bse;
        const float* w = (i == 0) ? W0 : (i == 1) ? W1 : (i == 2) ? W2 : (i == 3) ? W3 : W4;
        float v = s_urep[i * DD + lane]      * __ldg(&w[r * DD + lane])
                + s_urep[i * DD + 32 + lane] * __ldg(&w[r * DD + 32 + lane]);
#pragma unroll
        for (int m = 16; m >= 1; m >>= 1) v += __shfl_xor_sync(0xffffffffu, v, m);
        if (lane == 0) s_wu[j] = v * s_deninv[i];
    }
    __syncthreads();

    // ================= Phase 6: group softmax + CE ==========================
    if (t < 5) {
        int c0 = (t == 0) ? 0 : (t == 1) ? 2 : (t == 2) ? 6 : (t == 3) ? 10 : 12;
        int n  = (t == 0) ? 2 : (t == 1) ? 4 : (t == 2) ? 4 : (t == 3) ? 2 : 6;
        float m = -1e30f;
#pragma unroll 6
        for (int j = 0; j < 6; ++j) if (j < n) m = fmaxf(m, s_wu[c0 + j]);
        float ex[6], sum = 0.f;
#pragma unroll 6
        for (int j = 0; j < 6; ++j) {
            ex[j] = (j < n) ? __expf(s_wu[c0 + j] - m) : 0.f;
            sum += ex[j];
        }
        float inv = 1.0f / sum;
        float lse = __logf(sum);
        float li = 0.f;
#pragma unroll 6
        for (int j = 0; j < 6; ++j) {
            if (j < n) {
                out[b * NOUT + c0 + j] = ex[j] * inv;
                float logp = s_wu[c0 + j] - m - lse;
                li -= logp * __ldg(&y[b * NOUT + c0 + j]);
            }
        }
        s_lossi[t] = li;
    }
    __syncthreads();

    // ================= fused loss reduction (last block) ====================
    if (t == 0) {
        float loss = s_lossi[0] + s_lossi[1] + s_lossi[2] + s_lossi[3] + s_lossi[4];
        __stcg(&g_loss_part[b], loss);
        __threadfence();
        unsigned old = atomicAdd(&g_ticket, 1u);
        s_last = (old == gridDim.x - 1) ? 1 : 0;
    }
    __syncthreads();
    if (s_last) {
        int B = gridDim.x;
        float v = 0.f;
        for (int i = t; i < B; i += NT) v += __ldcg(&g_loss_part[i]);
        s_red[t] = v;
        __syncthreads();
        for (int s = NT / 2; s > 0; s >>= 1) {
            if (t < s) s_red[t] += s_red[t + s];
            __syncthreads();
        }
        if (t == 0) {
            out[out_size - 1] = s_red[0] / (float)B;
            g_ticket = 0;   // reset for next graph replay
        }
    }
}

extern "C" void kernel_launch(void* const* d_in, const int* in_sizes, int n_in,
                              void* d_out, int out_size)
{
    const int*   x    = (const int*)d_in[0];
    const float* y    = (const float*)d_in[1];
    const float* emb  = (const float*)d_in[2];
    const float* attw = (const float*)d_in[3];
    const float* attb = (const float*)d_in[4];
    const float* W0   = (const float*)d_in[5];
    const float* W1   = (const float*)d_in[6];
    const float* W2   = (const float*)d_in[7];
    const float* W3   = (const float*)d_in[8];
    const float* W4   = (const float*)d_in[9];
    float* out = (float*)d_out;

    int B = in_sizes[0] / SS;   // 4096
    size_t dyn_bytes = (size_t)DYN_FLOATS * sizeof(float);   // 62080

    static int attr_set = 0;
    if (!attr_set) {
        cudaFuncSetAttribute(tan_kernel,
                             cudaFuncAttributeMaxDynamicSharedMemorySize,
                             (int)dyn_bytes);
        attr_set = 1;
    }

    tan_kernel<<<B, NT, dyn_bytes>>>(x, y, emb, attw, attb,
                                     W0, W1, W2, W3, W4, out, out_size);
}

// round 3
// speedup vs baseline: 1.2021x; 1.2021x over previous
#include <cuda_runtime.h>
#include <cstdint>

#define SS 200
#define DD 64
#define NOUT 18
#define NT 256
#define NITER 13            // ceil(200 / 16) row-groups of 16

typedef unsigned long long ull;

// dynamic smem layout (floats):
//   [0, 12800)        s_emb  200 rows x 64 floats, 16B-granule XOR swizzled
//                     (aliased by reduce scratch after phase B)
//   [12800, 14400)    s_p    200 x 8   (p0..p4 per row, float4-aligned)
//   [14400, 14720)    s_aw   5 x 64
#define OFF_EMB 0
#define OFF_P   12800
#define OFF_AW  14400
#define OFF_SCR 0            // scratch aliases s_emb (dead after phase B)
#define DYN_FLOATS 14720

__device__ float g_loss_part[4096];
__device__ unsigned int g_ticket = 0;

__device__ __forceinline__ ull ffma2(ull a, ull b, ull c) {
    ull d; asm("fma.rn.f32x2 %0, %1, %2, %3;" : "=l"(d) : "l"(a), "l"(b), "l"(c)); return d;
}
__device__ __forceinline__ ull fadd2(ull a, ull b) {
    ull d; asm("add.rn.f32x2 %0, %1, %2;" : "=l"(d) : "l"(a), "l"(b)); return d;
}
__device__ __forceinline__ ull pack2(float x, float y) {
    ull r; asm("mov.b64 %0, {%1, %2};" : "=l"(r) : "f"(x), "f"(y)); return r;
}
__device__ __forceinline__ void unpack2(ull v, float& x, float& y) {
    asm("mov.b64 {%0, %1}, %2;" : "=f"(x), "=f"(y) : "l"(v));
}

__global__ __launch_bounds__(NT, 2) void tan_kernel(
    const int* __restrict__ x, const float* __restrict__ y,
    const float* __restrict__ emb, const float* __restrict__ attw,
    const float* __restrict__ attb,
    const float* __restrict__ W0, const float* __restrict__ W1,
    const float* __restrict__ W2, const float* __restrict__ W3,
    const float* __restrict__ W4,
    float* __restrict__ out, int out_size)
{
    extern __shared__ float dyn[];
    __shared__ int   s_x[SS];
    __shared__ float s_dcomb[8 * 5];
    __shared__ float s_urep[5 * DD];
    __shared__ float s_deninv[5];
    __shared__ float s_wu[NOUT];
    __shared__ float s_lossi[5];
    __shared__ float s_red[NT];
    __shared__ int   s_last;

    const int b    = blockIdx.x;
    const int t    = threadIdx.x;
    const int lane = t & 31;
    const int warp = t >> 5;
    const int q    = t & 15;      // granule index within a row (16B chunks)
    const int slot = t >> 4;      // which of 16 rows per iteration

    const uint32_t sbase = (uint32_t)__cvta_generic_to_shared(dyn);
    const uint32_t a_emb = sbase + OFF_EMB * 4;
    const uint32_t a_p   = sbase + OFF_P * 4;
    const uint32_t a_aw  = sbase + OFF_AW * 4;
    const uint32_t a_scr = sbase + OFF_SCR * 4;

    // ---- stage x row + attention weights ----
    for (int i = t; i < SS; i += NT) s_x[i] = x[b * SS + i];
    if (t < 64) {
#pragma unroll
        for (int k = 0; k < 5; ++k)
            dyn[OFF_AW + k * 64 + t] = __ldg(&attw[k * DD + t]);
    }
    __syncthreads();

    // ================= Phase A: coalesced gather, keep in regs + stage smem ====
    ull e01[NITER], e23[NITER];
#pragma unroll
    for (int i = 0; i < NITER; ++i) {
        int row = i * 16 + slot;
        e01[i] = 0ull; e23[i] = 0ull;
        if (row < SS) {
            const float* gp = emb + (size_t)s_x[row] * DD + q * 4;
            asm("ld.global.nc.v2.u64 {%0, %1}, [%2];"
                : "=l"(e01[i]), "=l"(e23[i]) : "l"(gp));
        }
    }
#pragma unroll
    for (int i = 0; i < NITER; ++i) {
        int row = i * 16 + slot;
        if (row < SS) {
            uint32_t dst = a_emb + (uint32_t)(row * 256 + ((q ^ (row & 15)) * 16));
            asm volatile("st.shared.v2.u64 [%0], {%1, %2};"
                         :: "r"(dst), "l"(e01[i]), "l"(e23[i]));
        }
    }
    __syncthreads();

    // ================= Phase B: scores (thread = row) ==========================
    if (t < SS) {
        ull su[5];
#pragma unroll
        for (int k = 0; k < 5; ++k) su[k] = 0ull;
        const uint32_t rbase = a_emb + (uint32_t)(t * 256);
        const int tx = t & 15;
#pragma unroll 4
        for (int c = 0; c < 16; ++c) {
            ull g01, g23;
            asm("ld.shared.v2.u64 {%0, %1}, [%2];"
                : "=l"(g01), "=l"(g23) : "r"(rbase + (uint32_t)((c ^ tx) * 16)));
#pragma unroll
            for (int k = 0; k < 5; ++k) {
                ull w01, w23;
                asm("ld.shared.v2.u64 {%0, %1}, [%2];"
                    : "=l"(w01), "=l"(w23) : "r"(a_aw + (uint32_t)(k * 256 + c * 16)));
                su[k] = ffma2(g01, w01, su[k]);
                su[k] = ffma2(g23, w23, su[k]);
            }
        }
        float p[5];
#pragma unroll
        for (int k = 0; k < 5; ++k) {
            float lo, hi;
            unpack2(su[k], lo, hi);
            float u  = lo + hi + __ldg(&attb[k]);
            float ex = __expf(2.0f * u);
            float th = 1.0f - __fdividef(2.0f, ex + 1.0f);
            p[k] = __expf(th);                 // exp(tanh(u)), no max-sub needed
        }
        float4 pv = make_float4(p[0], p[1], p[2], p[3]);
        *(float4*)&dyn[OFF_P + t * 8] = pv;
        dyn[OFF_P + t * 8 + 4] = p[4];
    }
    __syncthreads();

    // ================= Phase C: accumulate from registers ======================
    ull ac01[5], ac23[5];
    float ds[5];
#pragma unroll
    for (int k = 0; k < 5; ++k) { ac01[k] = 0ull; ac23[k] = 0ull; ds[k] = 0.f; }
#pragma unroll
    for (int i = 0; i < NITER; ++i) {
        int row = i * 16 + slot;
        if (row < SS) {
            float4 pv = *(const float4*)&dyn[OFF_P + row * 8];
            float  p4 = dyn[OFF_P + row * 8 + 4];
            ull pk;
            pk = pack2(pv.x, pv.x); ac01[0] = ffma2(e01[i], pk, ac01[0]); ac23[0] = ffma2(e23[i], pk, ac23[0]);
            pk = pack2(pv.y, pv.y); ac01[1] = ffma2(e01[i], pk, ac01[1]); ac23[1] = ffma2(e23[i], pk, ac23[1]);
            pk = pack2(pv.z, pv.z); ac01[2] = ffma2(e01[i], pk, ac01[2]); ac23[2] = ffma2(e23[i], pk, ac23[2]);
            pk = pack2(pv.w, pv.w); ac01[3] = ffma2(e01[i], pk, ac01[3]); ac23[3] = ffma2(e23[i], pk, ac23[3]);
            pk = pack2(p4,   p4);   ac01[4] = ffma2(e01[i], pk, ac01[4]); ac23[4] = ffma2(e23[i], pk, ac23[4]);
            ds[0] += pv.x; ds[1] += pv.y; ds[2] += pv.z; ds[3] += pv.w; ds[4] += p4;
        }
    }

    // reduce slot-pairs within warp (lanes l <-> l+16 hold the two slots)
#pragma unroll
    for (int k = 0; k < 5; ++k) {
        ac01[k] = fadd2(ac01[k], __shfl_xor_sync(0xffffffffu, ac01[k], 16));
        ac23[k] = fadd2(ac23[k], __shfl_xor_sync(0xffffffffu, ac23[k], 16));
        ds[k]  += __shfl_xor_sync(0xffffffffu, ds[k], 16);
    }
    // lanes 0..15: q = lane. write per-warp partials to scratch (aliases s_emb)
    if (lane < 16) {
#pragma unroll
        for (int k = 0; k < 5; ++k) {
            uint32_t addr = a_scr + (uint32_t)(((warp * 16 + lane) * 5 + k) * 16);
            asm volatile("st.shared.v2.u64 [%0], {%1, %2};"
                         :: "r"(addr), "l"(ac01[k]), "l"(ac23[k]));
        }
    }
    if (lane == 0) {
#pragma unroll
        for (int k = 0; k < 5; ++k) s_dcomb[warp * 5 + k] = ds[k];
    }
    __syncthreads();

    if (t < 5) {
        float dn = 0.f;
#pragma unroll
        for (int w = 0; w < 8; ++w) dn += s_dcomb[w * 5 + t];
        s_deninv[t] = 1.0f / dn;
    }
    if (t < 160) {
        int k = t >> 5, d2 = t & 31;      // d2 = q*2 + h
        int qq = d2 >> 1, h = d2 & 1;
        float sx = 0.f, sy = 0.f;
#pragma unroll
        for (int w = 0; w < 8; ++w) {
            float2 v = *(const float2*)&dyn[OFF_SCR + ((w * 16 + qq) * 5 + k) * 4 + h * 2];
            sx += v.x; sy += v.y;
        }
        s_urep[k * DD + d2 * 2]     = sx;
        s_urep[k * DD + d2 * 2 + 1] = sy;
    }
    __syncthreads();

    // ================= Phase 5: W_user = user_rep @ Wi^T =======================
    for (int j = warp; j < NOUT; j += 8) {
        int i = (j < 2) ? 0 : (j < 6) ? 1 : (j < 10) ? 2 : (j < 12) ? 3 : 4;
        int bse = (i == 0) ? 0 : (i == 1) ? 2 : (i == 2) ? 6 : (i == 3) ? 10 : 12;
        int r = j - bse;
        const float* w = (i == 0) ? W0 : (i == 1) ? W1 : (i == 2) ? W2 : (i == 3) ? W3 : W4;
        float v = s_urep[i * DD + lane]      * __ldg(&w[r * DD + lane])
                + s_urep[i * DD + 32 + lane] * __ldg(&w[r * DD + 32 + lane]);
#pragma unroll
        for (int m = 16; m >= 1; m >>= 1) v += __shfl_xor_sync(0xffffffffu, v, m);
        if (lane == 0) s_wu[j] = v * s_deninv[i];
    }
    __syncthreads();

    // ================= Phase 6: group softmax + CE =============================
    if (t < 5) {
        int c0 = (t == 0) ? 0 : (t == 1) ? 2 : (t == 2) ? 6 : (t == 3) ? 10 : 12;
        int n  = (t == 0) ? 2 : (t == 1) ? 4 : (t == 2) ? 4 : (t == 3) ? 2 : 6;
        float m = -1e30f;
#pragma unroll 6
        for (int j = 0; j < 6; ++j) if (j < n) m = fmaxf(m, s_wu[c0 + j]);
        float ex[6], sum = 0.f;
#pragma unroll 6
        for (int j = 0; j < 6; ++j) {
            ex[j] = (j < n) ? __expf(s_wu[c0 + j] - m) : 0.f;
            sum += ex[j];
        }
        float inv = 1.0f / sum;
        float lse = __logf(sum);
        float li = 0.f;
#pragma unroll 6
        for (int j = 0; j < 6; ++j) {
            if (j < n) {
                out[b * NOUT + c0 + j] = ex[j] * inv;
                float logp = s_wu[c0 + j] - m - lse;
                li -= logp * __ldg(&y[b * NOUT + c0 + j]);
            }
        }
        s_lossi[t] = li;
    }
    __syncthreads();

    // ================= fused loss reduction (last block) =======================
    if (t == 0) {
        float loss = s_lossi[0] + s_lossi[1] + s_lossi[2] + s_lossi[3] + s_lossi[4];
        __stcg(&g_loss_part[b], loss);
        __threadfence();
        unsigned old = atomicAdd(&g_ticket, 1u);
        s_last = (old == gridDim.x - 1) ? 1 : 0;
    }
    __syncthreads();
    if (s_last) {
        int B = gridDim.x;
        float v = 0.f;
        for (int i = t; i < B; i += NT) v += __ldcg(&g_loss_part[i]);
        s_red[t] = v;
        __syncthreads();
        for (int s = NT / 2; s > 0; s >>= 1) {
            if (t < s) s_red[t] += s_red[t + s];
            __syncthreads();
        }
        if (t == 0) {
            out[out_size - 1] = s_red[0] / (float)B;
            g_ticket = 0;   // reset for next graph replay
        }
    }
}

extern "C" void kernel_launch(void* const* d_in, const int* in_sizes, int n_in,
                              void* d_out, int out_size)
{
    const int*   x    = (const int*)d_in[0];
    const float* y    = (const float*)d_in[1];
    const float* emb  = (const float*)d_in[2];
    const float* attw = (const float*)d_in[3];
    const float* attb = (const float*)d_in[4];
    const float* W0   = (const float*)d_in[5];
    const float* W1   = (const float*)d_in[6];
    const float* W2   = (const float*)d_in[7];
    const float* W3   = (const float*)d_in[8];
    const float* W4   = (const float*)d_in[9];
    float* out = (float*)d_out;

    int B = in_sizes[0] / SS;   // 4096
    size_t dyn_bytes = (size_t)DYN_FLOATS * sizeof(float);   // 58880

    static int attr_set = 0;
    if (!attr_set) {
        cudaFuncSetAttribute(tan_kernel,
                             cudaFuncAttributeMaxDynamicSharedMemorySize,
                             (int)dyn_bytes);
        attr_set = 1;
    }

    tan_kernel<<<B, NT, dyn_bytes>>>(x, y, emb, attw, attb,
                                     W0, W1, W2, W3, W4, out, out_size);
}

// round 5
// speedup vs baseline: 1.3509x; 1.1238x over previous
#include <cuda_runtime.h>
#include <cstdint>

#define SS 200
#define DD 64
#define NOUT 18
#define NT 256
#define CHUNK 100
#define STRIDE 68          // padded floats per embed row (conflict-free)
#define NITER_A 7          // ceil(100/16) row-groups of 16

typedef unsigned long long ull;

// dynamic smem layout (floats):
//   [0, 6800)      s_emb  100 rows x 68 floats   (aliased by scr after last use)
//   [6800, 7600)   s_p    100 x 8
//   [7600, 7920)   s_aw   5 x 64
#define OFF_EMB 0
#define OFF_P   6800
#define OFF_AW  7600
#define OFF_SCR 0
#define DYN_FLOATS 7920

__device__ float g_loss_part[4096];
__device__ unsigned int g_ticket = 0;

__device__ __forceinline__ ull ffma2(ull a, ull b, ull c) {
    ull d; asm("fma.rn.f32x2 %0, %1, %2, %3;" : "=l"(d) : "l"(a), "l"(b), "l"(c)); return d;
}
__device__ __forceinline__ ull pack2(float x, float y) {
    ull r; asm("mov.b64 %0, {%1, %2};" : "=l"(r) : "f"(x), "f"(y)); return r;
}
__device__ __forceinline__ void unpack2(ull v, float& x, float& y) {
    asm("mov.b64 {%0, %1}, %2;" : "=f"(x), "=f"(y) : "l"(v));
}

__global__ __launch_bounds__(NT, 5) void tan_kernel(
    const int* __restrict__ x, const float* __restrict__ y,
    const float* __restrict__ emb, const float* __restrict__ attw,
    const float* __restrict__ attb,
    const float* __restrict__ W0, const float* __restrict__ W1,
    const float* __restrict__ W2, const float* __restrict__ W3,
    const float* __restrict__ W4,
    float* __restrict__ out, int out_size)
{
    extern __shared__ float dyn[];
    __shared__ int   s_x[SS];
    __shared__ float s_attb[5];
    __shared__ float s_dcomb[8 * 5];
    __shared__ float s_urep[5 * DD];
    __shared__ float s_deninv[5];
    __shared__ float s_wu[NOUT];
    __shared__ float s_lossi[5];
    __shared__ float s_red[NT];
    __shared__ int   s_last;

    const int b    = blockIdx.x;
    const int t    = threadIdx.x;
    const int lane = t & 31;
    const int warp = t >> 5;
    const int q    = t & 15;      // 16B-chunk index within a row
    const int slot = t >> 4;      // row-within-group (0..15)

    const uint32_t sbase = (uint32_t)__cvta_generic_to_shared(dyn);
    const uint32_t a_emb = sbase + OFF_EMB * 4;
    const uint32_t a_aw  = sbase + OFF_AW * 4;
    const uint32_t a_scr = sbase + OFF_SCR * 4;

    // ---- stage x row, attention weights, bias ----
    for (int i = t; i < SS; i += NT) s_x[i] = x[b * SS + i];
    if (t < 64) {
#pragma unroll
        for (int k = 0; k < 5; ++k)
            dyn[OFF_AW + k * 64 + t] = __ldg(&attw[k * DD + t]);
    }
    if (t < 5) s_attb[t] = __ldg(&attb[t]);
    __syncthreads();

    // packed accumulators: lane = d-pair, 5 groups; persist across chunks
    ull   ac[5];
    float ds[5];
#pragma unroll
    for (int k = 0; k < 5; ++k) { ac[k] = 0ull; ds[k] = 0.f; }

    for (int ch = 0; ch < 2; ++ch) {
        // ===== Phase A: coalesced gather into padded smem tile =====
#pragma unroll
        for (int i = 0; i < NITER_A; ++i) {
            int row = i * 16 + slot;
            if (row < CHUNK) {
                float4 e = __ldg((const float4*)&emb[(size_t)s_x[ch * CHUNK + row] * DD + q * 4]);
                *(float4*)&dyn[OFF_EMB + row * STRIDE + q * 4] = e;
            }
        }
        __syncthreads();

        // ===== Phase B: scores (thread = row), FFMA2 dot =====
        if (t < CHUNK) {
            ull su[5];
#pragma unroll
            for (int k = 0; k < 5; ++k) su[k] = 0ull;
            const uint32_t rbase = a_emb + (uint32_t)(t * STRIDE) * 4;
#pragma unroll 4
            for (int c = 0; c < 16; ++c) {
                ull g01, g23;
                asm("ld.shared.v2.u64 {%0, %1}, [%2];"
                    : "=l"(g01), "=l"(g23) : "r"(rbase + (uint32_t)(c * 16)));
#pragma unroll
                for (int k = 0; k < 5; ++k) {
                    ull w01, w23;
                    asm("ld.shared.v2.u64 {%0, %1}, [%2];"
                        : "=l"(w01), "=l"(w23) : "r"(a_aw + (uint32_t)(k * 256 + c * 16)));
                    su[k] = ffma2(g01, w01, su[k]);
                    su[k] = ffma2(g23, w23, su[k]);
                }
            }
            float p[5];
#pragma unroll
            for (int k = 0; k < 5; ++k) {
                float lo, hi;
                unpack2(su[k], lo, hi);
                float u  = lo + hi + s_attb[k];
                float ex = __expf(2.0f * u);
                float th = 1.0f - __fdividef(2.0f, ex + 1.0f);
                p[k] = __expf(th);                 // exp(tanh(u)); |tanh|<=1, no max-sub
            }
            *(float4*)&dyn[OFF_P + t * 8] = make_float4(p[0], p[1], p[2], p[3]);
            dyn[OFF_P + t * 8 + 4] = p[4];
        }
        __syncthreads();

        // ===== Phase C: accumulate numerators/denominators (warp-strided rows) =====
        for (int s = warp; s < CHUNK; s += 8) {
            float4 pv = *(const float4*)&dyn[OFF_P + s * 8];
            float  p4 = dyn[OFF_P + s * 8 + 4];
            ull e2;
            asm("ld.shared.b64 %0, [%1];"
                : "=l"(e2) : "r"(a_emb + (uint32_t)(s * STRIDE + lane * 2) * 4));
            ac[0] = ffma2(e2, pack2(pv.x, pv.x), ac[0]);
            ac[1] = ffma2(e2, pack2(pv.y, pv.y), ac[1]);
            ac[2] = ffma2(e2, pack2(pv.z, pv.z), ac[2]);
            ac[3] = ffma2(e2, pack2(pv.w, pv.w), ac[3]);
            ac[4] = ffma2(e2, pack2(p4,   p4),   ac[4]);
            ds[0] += pv.x; ds[1] += pv.y; ds[2] += pv.z; ds[3] += pv.w; ds[4] += p4;
        }
        __syncthreads();   // emb reads done: chunk 0 -> refill; chunk 1 -> scr alias safe
    }

    // ---- per-warp partials into scratch (aliases emb tile) ----
#pragma unroll
    for (int k = 0; k < 5; ++k) {
        uint32_t addr = a_scr + (uint32_t)(((warp * 5 + k) * 32 + lane) * 8);
        asm volatile("st.shared.u64 [%0], %1;" :: "r"(addr), "l"(ac[k]));
    }
    if (lane == 0) {
#pragma unroll
        for (int k = 0; k < 5; ++k) s_dcomb[warp * 5 + k] = ds[k];
    }
    __syncthreads();

    if (t < 5) {
        float dn = 0.f;
#pragma unroll
        for (int w = 0; w < 8; ++w) dn += s_dcomb[w * 5 + t];
        s_deninv[t] = 1.0f / dn;
    }
    if (t < 160) {
        int k = t >> 5, d2 = t & 31;
        float sx = 0.f, sy = 0.f;
#pragma unroll
        for (int w = 0; w < 8; ++w) {
            float2 v = *(const float2*)&dyn[OFF_SCR + ((w * 5 + k) * 32 + d2) * 2];
            sx += v.x; sy += v.y;
        }
        s_urep[k * DD + d2 * 2]     = sx;
        s_urep[k * DD + d2 * 2 + 1] = sy;
    }
    __syncthreads();

    // ===== Phase 5: W_user = user_rep @ Wi^T =====
    for (int j = warp; j < NOUT; j += 8) {
        int i = (j < 2) ? 0 : (j < 6) ? 1 : (j < 10) ? 2 : (j < 12) ? 3 : 4;
        int bse = (i == 0) ? 0 : (i == 1) ? 2 : (i == 2) ? 6 : (i == 3) ? 10 : 12;
        int r = j - bse;
        const float* w = (i == 0) ? W0 : (i == 1) ? W1 : (i == 2) ? W2 : (i == 3) ? W3 : W4;
        float v = s_urep[i * DD + lane]      * __ldg(&w[r * DD + lane])
                + s_urep[i * DD + 32 + lane] * __ldg(&w[r * DD + 32 + lane]);
#pragma unroll
        for (int m = 16; m >= 1; m >>= 1) v += __shfl_xor_sync(0xffffffffu, v, m);
        if (lane == 0) s_wu[j] = v * s_deninv[i];
    }
    __syncthreads();

    // ===== Phase 6: group softmax + CE =====
    if (t < 5) {
        int c0 = (t == 0) ? 0 : (t == 1) ? 2 : (t == 2) ? 6 : (t == 3) ? 10 : 12;
        int n  = (t == 0) ? 2 : (t == 1) ? 4 : (t == 2) ? 4 : (t == 3) ? 2 : 6;
        float m = -1e30f;
#pragma unroll 6
        for (int j = 0; j < 6; ++j) if (j < n) m = fmaxf(m, s_wu[c0 + j]);
        float ex[6], sum = 0.f;
#pragma unroll 6
        for (int j = 0; j < 6; ++j) {
            ex[j] = (j < n) ? __expf(s_wu[c0 + j] - m) : 0.f;
            sum += ex[j];
        }
        float inv = 1.0f / sum;
        float lse = __logf(sum);
        float li = 0.f;
#pragma unroll 6
        for (int j = 0; j < 6; ++j) {
            if (j < n) {
                out[b * NOUT + c0 + j] = ex[j] * inv;
                float logp = s_wu[c0 + j] - m - lse;
                li -= logp * __ldg(&y[b * NOUT + c0 + j]);
            }
        }
        s_lossi[t] = li;
    }
    __syncthreads();

    // ===== fused deterministic loss reduction (last block) =====
    if (t == 0) {
        float loss = s_lossi[0] + s_lossi[1] + s_lossi[2] + s_lossi[3] + s_lossi[4];
        __stcg(&g_loss_part[b], loss);
        __threadfence();
        unsigned old = atomicAdd(&g_ticket, 1u);
        s_last = (old == gridDim.x - 1) ? 1 : 0;
    }
    __syncthreads();
    if (s_last) {
        int B = gridDim.x;
        float v = 0.f;
        for (int i = t; i < B; i += NT) v += __ldcg(&g_loss_part[i]);
        s_red[t] = v;
        __syncthreads();
        for (int s = NT / 2; s > 0; s >>= 1) {
            if (t < s) s_red[t] += s_red[t + s];
            __syncthreads();
        }
        if (t == 0) {
            out[out_size - 1] = s_red[0] / (float)B;
            g_ticket = 0;   // reset for next graph replay
        }
    }
}

extern "C" void kernel_launch(void* const* d_in, const int* in_sizes, int n_in,
                              void* d_out, int out_size)
{
    const int*   x    = (const int*)d_in[0];
    const float* y    = (const float*)d_in[1];
    const float* emb  = (const float*)d_in[2];
    const float* attw = (const float*)d_in[3];
    const float* attb = (const float*)d_in[4];
    const float* W0   = (const float*)d_in[5];
    const float* W1   = (const float*)d_in[6];
    const float* W2   = (const float*)d_in[7];
    const float* W3   = (const float*)d_in[8];
    const float* W4   = (const float*)d_in[9];
    float* out = (float*)d_out;

    int B = in_sizes[0] / SS;   // 4096
    size_t dyn_bytes = (size_t)DYN_FLOATS * sizeof(float);   // 31680

    static int attr_set = 0;
    if (!attr_set) {
        cudaFuncSetAttribute(tan_kernel,
                             cudaFuncAttributeMaxDynamicSharedMemorySize,
                             (int)dyn_bytes);
        attr_set = 1;
    }

    tan_kernel<<<B, NT, dyn_bytes>>>(x, y, emb, attw, attb,
                                     W0, W1, W2, W3, W4, out, out_size);
}

// round 7
// speedup vs baseline: 1.7487x; 1.2945x over previous
#include <cuda_runtime.h>
#include <cstdint>

#define SS 200
#define DD 64
#define NOUT 18
#define NT 256
#define CHUNK 100
#define STRIDE 68          // padded floats per embed row (conflict-free)
#define NITER_A 7          // ceil(100/16) row-groups of 16

typedef unsigned long long ull;

// dynamic smem layout (floats):
//   [0, 6800)      s_emb  100 rows x 68 floats   (aliased by scr after last use)
//   [6800, 7600)   s_p    100 x 8
#define OFF_EMB 0
#define OFF_P   6800
#define OFF_SCR 0
#define DYN_FLOATS 7600

__constant__ float c_attw[5][DD];
__constant__ float c_attb[5];

__device__ float g_loss_part[4096];
__device__ unsigned int g_ticket = 0;

__device__ __forceinline__ ull ffma2(ull a, ull b, ull c) {
    ull d; asm("fma.rn.f32x2 %0, %1, %2, %3;" : "=l"(d) : "l"(a), "l"(b), "l"(c)); return d;
}
__device__ __forceinline__ ull pack2(float x, float y) {
    ull r; asm("mov.b64 %0, {%1, %2};" : "=l"(r) : "f"(x), "f"(y)); return r;
}
__device__ __forceinline__ void unpack2(ull v, float& x, float& y) {
    asm("mov.b64 {%0, %1}, %2;" : "=f"(x), "=f"(y) : "l"(v));
}

__global__ __launch_bounds__(NT, 6) void tan_kernel(
    const int* __restrict__ x, const float* __restrict__ y,
    const float* __restrict__ emb,
    const float* __restrict__ W0, const float* __restrict__ W1,
    const float* __restrict__ W2, const float* __restrict__ W3,
    const float* __restrict__ W4,
    float* __restrict__ out, int out_size)
{
    extern __shared__ float dyn[];
    __shared__ int   s_x[SS];
    __shared__ float s_dcomb[8 * 5];
    __shared__ float s_urep[5 * DD];
    __shared__ float s_deninv[5];
    __shared__ float s_wu[NOUT];
    __shared__ float s_lossi[5];
    __shared__ float s_red[NT];
    __shared__ int   s_last;

    const int b    = blockIdx.x;
    const int t    = threadIdx.x;
    const int lane = t & 31;
    const int warp = t >> 5;
    const int q    = t & 15;      // 16B-chunk index within a row
    const int slot = t >> 4;      // row-within-group (0..15)

    const uint32_t sbase = (uint32_t)__cvta_generic_to_shared(dyn);
    const uint32_t a_emb = sbase + OFF_EMB * 4;
    const uint32_t a_scr = sbase + OFF_SCR * 4;

    // ---- stage x row ----
    for (int i = t; i < SS; i += NT) s_x[i] = x[b * SS + i];
    __syncthreads();

    // packed accumulators: lane = d-pair, 5 groups; persist across chunks
    ull   ac[5];
    float ds[5];
#pragma unroll
    for (int k = 0; k < 5; ++k) { ac[k] = 0ull; ds[k] = 0.f; }

    for (int ch = 0; ch < 2; ++ch) {
        // ===== Phase A: coalesced gather into padded smem tile =====
#pragma unroll
        for (int i = 0; i < NITER_A; ++i) {
            int row = i * 16 + slot;
            if (row < CHUNK) {
                float4 e = __ldg((const float4*)&emb[(size_t)s_x[ch * CHUNK + row] * DD + q * 4]);
                *(float4*)&dyn[OFF_EMB + row * STRIDE + q * 4] = e;
            }
        }
        __syncthreads();

        // ===== Phase B: scores (thread = row); weights from __constant__ =====
        if (t < CHUNK) {
            ull su[5];
#pragma unroll
            for (int k = 0; k < 5; ++k) su[k] = 0ull;
            const uint32_t rbase = a_emb + (uint32_t)(t * STRIDE) * 4;
#pragma unroll 4
            for (int c = 0; c < 16; ++c) {
                ull g01, g23;
                asm("ld.shared.v2.u64 {%0, %1}, [%2];"
                    : "=l"(g01), "=l"(g23) : "r"(rbase + (uint32_t)(c * 16)));
#pragma unroll
                for (int k = 0; k < 5; ++k) {
                    float2 w01 = *(const float2*)&c_attw[k][c * 4];
                    float2 w23 = *(const float2*)&c_attw[k][c * 4 + 2];
                    su[k] = ffma2(g01, pack2(w01.x, w01.y), su[k]);
                    su[k] = ffma2(g23, pack2(w23.x, w23.y), su[k]);
                }
            }
            float p[5];
#pragma unroll
            for (int k = 0; k < 5; ++k) {
                float lo, hi;
                unpack2(su[k], lo, hi);
                float u = lo + hi + c_attb[k];
                p[k] = __expf(__tanhf(u));     // |tanh|<=1, no max-sub needed
            }
            *(float4*)&dyn[OFF_P + t * 8] = make_float4(p[0], p[1], p[2], p[3]);
            dyn[OFF_P + t * 8 + 4] = p[4];
        }
        __syncthreads();

        // ===== Phase C: accumulate numerators/denominators (warp-strided rows) =====
        for (int s = warp; s < CHUNK; s += 8) {
            float4 pv = *(const float4*)&dyn[OFF_P + s * 8];
            float  p4 = dyn[OFF_P + s * 8 + 4];
            ull e2;
            asm("ld.shared.b64 %0, [%1];"
                : "=l"(e2) : "r"(a_emb + (uint32_t)(s * STRIDE + lane * 2) * 4));
            ac[0] = ffma2(e2, pack2(pv.x, pv.x), ac[0]);
            ac[1] = ffma2(e2, pack2(pv.y, pv.y), ac[1]);
            ac[2] = ffma2(e2, pack2(pv.z, pv.z), ac[2]);
            ac[3] = ffma2(e2, pack2(pv.w, pv.w), ac[3]);
            ac[4] = ffma2(e2, pack2(p4,   p4),   ac[4]);
            ds[0] += pv.x; ds[1] += pv.y; ds[2] += pv.z; ds[3] += pv.w; ds[4] += p4;
        }
        __syncthreads();   // emb reads done: chunk 0 -> refill; chunk 1 -> scr alias safe
    }

    // ---- per-warp partials into scratch (aliases emb tile) ----
#pragma unroll
    for (int k = 0; k < 5; ++k) {
        uint32_t addr = a_scr + (uint32_t)(((warp * 5 + k) * 32 + lane) * 8);
        asm volatile("st.shared.u64 [%0], %1;" :: "r"(addr), "l"(ac[k]));
    }
    if (lane == 0) {
#pragma unroll
        for (int k = 0; k < 5; ++k) s_dcomb[warp * 5 + k] = ds[k];
    }
    __syncthreads();

    if (t < 5) {
        float dn = 0.f;
#pragma unroll
        for (int w = 0; w < 8; ++w) dn += s_dcomb[w * 5 + t];
        s_deninv[t] = 1.0f / dn;
    }
    if (t < 160) {
        int k = t >> 5, d2 = t & 31;
        float sx = 0.f, sy = 0.f;
#pragma unroll
        for (int w = 0; w < 8; ++w) {
            float2 v = *(const float2*)&dyn[OFF_SCR + ((w * 5 + k) * 32 + d2) * 2];
            sx += v.x; sy += v.y;
        }
        s_urep[k * DD + d2 * 2]     = sx;
        s_urep[k * DD + d2 * 2 + 1] = sy;
    }
    __syncthreads();

    // ===== Phase 5: W_user = user_rep @ Wi^T =====
    for (int j = warp; j < NOUT; j += 8) {
        int i = (j < 2) ? 0 : (j < 6) ? 1 : (j < 10) ? 2 : (j < 12) ? 3 : 4;
        int bse = (i == 0) ? 0 : (i == 1) ? 2 : (i == 2) ? 6 : (i == 3) ? 10 : 12;
        int r = j - bse;
        const float* w = (i == 0) ? W0 : (i == 1) ? W1 : (i == 2) ? W2 : (i == 3) ? W3 : W4;
        float v = s_urep[i * DD + lane]      * __ldg(&w[r * DD + lane])
                + s_urep[i * DD + 32 + lane] * __ldg(&w[r * DD + 32 + lane]);
#pragma unroll
        for (int m = 16; m >= 1; m >>= 1) v += __shfl_xor_sync(0xffffffffu, v, m);
        if (lane == 0) s_wu[j] = v * s_deninv[i];
    }
    __syncthreads();

    // ===== Phase 6: group softmax + CE =====
    if (t < 5) {
        int c0 = (t == 0) ? 0 : (t == 1) ? 2 : (t == 2) ? 6 : (t == 3) ? 10 : 12;
        int n  = (t == 0) ? 2 : (t == 1) ? 4 : (t == 2) ? 4 : (t == 3) ? 2 : 6;
        float m = -1e30f;
#pragma unroll 6
        for (int j = 0; j < 6; ++j) if (j < n) m = fmaxf(m, s_wu[c0 + j]);
        float ex[6], sum = 0.f;
#pragma unroll 6
        for (int j = 0; j < 6; ++j) {
            ex[j] = (j < n) ? __expf(s_wu[c0 + j] - m) : 0.f;
            sum += ex[j];
        }
        float inv = 1.0f / sum;
        float lse = __logf(sum);
        float li = 0.f;
#pragma unroll 6
        for (int j = 0; j < 6; ++j) {
            if (j < n) {
                out[b * NOUT + c0 + j] = ex[j] * inv;
                float logp = s_wu[c0 + j] - m - lse;
                li -= logp * __ldg(&y[b * NOUT + c0 + j]);
            }
        }
        s_lossi[t] = li;
    }
    __syncthreads();

    // ===== fused deterministic loss reduction (last block) =====
    if (t == 0) {
        float loss = s_lossi[0] + s_lossi[1] + s_lossi[2] + s_lossi[3] + s_lossi[4];
        __stcg(&g_loss_part[b], loss);
        __threadfence();
        unsigned old = atomicAdd(&g_ticket, 1u);
        s_last = (old == gridDim.x - 1) ? 1 : 0;
    }
    __syncthreads();
    if (s_last) {
        int B = gridDim.x;
        float v = 0.f;
        for (int i = t; i < B; i += NT) v += __ldcg(&g_loss_part[i]);
        s_red[t] = v;
        __syncthreads();
        for (int s = NT / 2; s > 0; s >>= 1) {
            if (t < s) s_red[t] += s_red[t + s];
            __syncthreads();
        }
        if (t == 0) {
            out[out_size - 1] = s_red[0] / (float)B;
            g_ticket = 0;   // reset for next graph replay
        }
    }
}

extern "C" void kernel_launch(void* const* d_in, const int* in_sizes, int n_in,
                              void* d_out, int out_size)
{
    const int*   x    = (const int*)d_in[0];
    const float* y    = (const float*)d_in[1];
    const float* emb  = (const float*)d_in[2];
    const float* attw = (const float*)d_in[3];
    const float* attb = (const float*)d_in[4];
    const float* W0   = (const float*)d_in[5];
    const float* W1   = (const float*)d_in[6];
    const float* W2   = (const float*)d_in[7];
    const float* W3   = (const float*)d_in[8];
    const float* W4   = (const float*)d_in[9];
    float* out = (float*)d_out;

    int B = in_sizes[0] / SS;   // 4096
    size_t dyn_bytes = (size_t)DYN_FLOATS * sizeof(float);   // 30400

    static int attr_set = 0;
    if (!attr_set) {
        cudaFuncSetAttribute(tan_kernel,
                             cudaFuncAttributeMaxDynamicSharedMemorySize,
                             (int)dyn_bytes);
        attr_set = 1;
    }

    // Stage attention weights/bias into __constant__ (D2D async: graph-capturable)
    cudaMemcpyToSymbolAsync(c_attw, attw, 5 * DD * sizeof(float), 0,
                            cudaMemcpyDeviceToDevice, 0);
    cudaMemcpyToSymbolAsync(c_attb, attb, 5 * sizeof(float), 0,
                            cudaMemcpyDeviceToDevice, 0);

    tan_kernel<<<B, NT, dyn_bytes>>>(x, y, emb,
                                     W0, W1, W2, W3, W4, out, out_size);
}